// round 3
// baseline (speedup 1.0000x reference)
#include <cuda_runtime.h>

// Problem constants (B=1, H=24, N=4096, D=128, F=256, CHUNK=128)
#define BH   24
#define SEQ  4096
#define DD   128
#define FF   256
#define CHK  128
#define NC   32
#define ROWS (BH*SEQ)      // 98304
#define FD   (FF*DD)       // 32768

// ---------------- scratch (device globals; no runtime allocation) ----------
__device__ float g_h   [(size_t)ROWS * FF];            // hidden (silu out)
__device__ float g_qphi[(size_t)ROWS * FF];
__device__ float g_kphi[(size_t)ROWS * FF];
__device__ float g_P   [(size_t)BH * (NC+1) * FD];     // prefix chunk states
__device__ float g_A   [(size_t)BH * NC * CHK * CHK];  // per-chunk score mats

// ---------------------------------------------------------------------------
// Naive GEMM + bias (+ optional SiLU): one thread per output element.
// C[row,col] = act( sum_k A[row,k] * W[k,col] + bias[col] )
// ---------------------------------------------------------------------------
__global__ void gemm_naive(const float* __restrict__ A,
                           const float* __restrict__ W,
                           const float* __restrict__ bias,
                           float* __restrict__ C,
                           int M, int K, int Nn, int act)
{
    int idx = blockIdx.x * blockDim.x + threadIdx.x;
    if (idx >= M * Nn) return;
    int row = idx / Nn;
    int col = idx - row * Nn;
    const float* a = A + (size_t)row * K;
    float s = bias[col];
    for (int kk = 0; kk < K; kk++)
        s += a[kk] * W[(size_t)kk * Nn + col];
    if (act) s = s / (1.f + __expf(-s));
    C[(size_t)row * Nn + col] = s;
}

// ---------------------------------------------------------------------------
// Chunk state: S[h,c][f,d] = sum_{m in chunk} kphi[pos0+m,f] * v[pos0+m,d]
// One thread per (h,c,f,d). Writes slab (c+1) of g_P.
// ---------------------------------------------------------------------------
__global__ void chunk_state_naive(const float* __restrict__ kphi,
                                  const float* __restrict__ v,
                                  float* __restrict__ P)
{
    int idx = blockIdx.x * blockDim.x + threadIdx.x;   // < BH*NC*FF*DD
    if (idx >= BH * NC * FF * DD) return;
    int d = idx & (DD - 1);
    int f = (idx / DD) & (FF - 1);
    int c = (idx / (DD * FF)) & (NC - 1);
    int h = idx / (DD * FF * NC);
    int pos0 = h * SEQ + c * CHK;
    float s = 0.f;
    for (int m = 0; m < CHK; m++)
        s += kphi[(size_t)(pos0 + m) * FF + f] * v[(size_t)(pos0 + m) * DD + d];
    P[((size_t)h * (NC + 1) + (c + 1)) * FD + (size_t)f * DD + d] = s;
}

// ---------------------------------------------------------------------------
// In-place inclusive prefix over chunk slabs; slab 0 zeroed.
// After: P[h][c] = sum of chunk states 0..c-1 (exclusive prefix for chunk c)
// ---------------------------------------------------------------------------
__global__ void prefix_kernel(float* __restrict__ P)
{
    const int h = blockIdx.y;
    const int e = blockIdx.x * 256 + threadIdx.x;   // < FD
    float* base = P + (size_t)h * (NC + 1) * FD;
    base[e] = 0.f;
    float acc = 0.f;
    for (int c = 1; c <= NC; c++) {
        acc += base[(size_t)c * FD + e];
        base[(size_t)c * FD + e] = acc;
    }
}

// ---------------------------------------------------------------------------
// Per-chunk score matrix: A[h,c][n,m] = sum_f qphi[pos0+n,f] * kphi[pos0+m,f]
// One thread per (h,c,n,m).
// ---------------------------------------------------------------------------
__global__ void score_naive(const float* __restrict__ qphi,
                            const float* __restrict__ kphi,
                            float* __restrict__ Am)
{
    int idx = blockIdx.x * blockDim.x + threadIdx.x;   // < BH*NC*CHK*CHK
    if (idx >= BH * NC * CHK * CHK) return;
    int m = idx & (CHK - 1);
    int n = (idx / CHK) & (CHK - 1);
    int c = (idx / (CHK * CHK)) & (NC - 1);
    int h = idx / (CHK * CHK * NC);
    int pos0 = h * SEQ + c * CHK;
    const float* qr = qphi + (size_t)(pos0 + n) * FF;
    const float* kr = kphi + (size_t)(pos0 + m) * FF;
    float s = 0.f;
    for (int f = 0; f < FF; f++) s += qr[f] * kr[f];
    Am[idx] = s;
}

// ---------------------------------------------------------------------------
// Output: one thread per (h, n_glob, d).
//   a1 = sum_{m<=n local} A[n,m] v[m,d]  + sum_f qphi[n,f] * Wexc[f,d]
//   a2 = sum_{m>=n local} A[n,m] v[m,d]  + sum_f qphi[n,f] * (Wtot-Winc)[f,d]
//   out = a1/(pos+1) + a2/(SEQ-pos)
// ---------------------------------------------------------------------------
__global__ void out_naive(const float* __restrict__ qphi,
                          const float* __restrict__ v,
                          const float* __restrict__ P,
                          const float* __restrict__ Am,
                          float* __restrict__ out)
{
    int idx = blockIdx.x * blockDim.x + threadIdx.x;   // < BH*SEQ*DD
    if (idx >= BH * SEQ * DD) return;
    int d  = idx & (DD - 1);
    int ng = (idx / DD) & (SEQ - 1);
    int h  = idx / (DD * SEQ);
    int c  = ng / CHK;
    int nl = ng & (CHK - 1);
    int pos0 = h * SEQ + c * CHK;

    const float* Arow = Am + (((size_t)(h * NC + c) * CHK) + nl) * CHK;
    float a1 = 0.f, a2 = 0.f;
    for (int m = 0; m <= nl; m++)
        a1 += Arow[m] * v[(size_t)(pos0 + m) * DD + d];
    for (int m = nl; m < CHK; m++)
        a2 += Arow[m] * v[(size_t)(pos0 + m) * DD + d];

    const float* Pb   = P + (size_t)h * (NC + 1) * FD;
    const float* Wexc = Pb + (size_t)c * FD;
    const float* Winc = Pb + (size_t)(c + 1) * FD;
    const float* Wtot = Pb + (size_t)NC * FD;
    const float* qr   = qphi + (size_t)(pos0 + nl) * FF;
    for (int f = 0; f < FF; f++) {
        float qv = qr[f];
        size_t o = (size_t)f * DD + d;
        a1 += qv * Wexc[o];
        a2 += qv * (Wtot[o] - Winc[o]);
    }
    out[idx] = a1 / (float)(ng + 1) + a2 / (float)(SEQ - ng);
}

// ---------------------------------------------------------------------------
extern "C" void kernel_launch(void* const* d_in, const int* in_sizes, int n_in,
                              void* d_out, int out_size)
{
    (void)out_size;
    // Size-signature classification; accepts element counts or byte counts.
    //   q/k/v : 12,582,912 elems (50,331,648 B)
    //   w1    : 32,768 (131,072 B);  w2 : 65,536 (262,144 B)
    //   b1/b2 : 256 (1,024 B)
    int big[3] = {0, 1, 2}; int nbig = 0;
    int iw1 = -1, iw2 = -1, ibias[2] = {-1, -1}; int nb = 0;
    for (int i = 0; i < n_in; i++) {
        long long s = in_sizes[i];
        if ((s == 12582912LL || s == 50331648LL) && nbig < 3) big[nbig++] = i;
        else if (s == 32768LL  || s == 131072LL) iw1 = i;
        else if (s == 65536LL  || s == 262144LL) iw2 = i;
        else if ((s == 256LL   || s == 1024LL) && nb < 2) ibias[nb++] = i;
    }
    // Fallback to insertion order if classification failed.
    if (nbig != 3 || iw1 < 0 || iw2 < 0 || nb != 2) {
        big[0] = 0; big[1] = 1; big[2] = 2;
        iw1 = 3; ibias[0] = 4; iw2 = 5; ibias[1] = 6;
    }
    const float *q, *k;
    if (big[0] == 0) {            // insertion order: q, k, v
        q = (const float*)d_in[big[0]];
        k = (const float*)d_in[big[1]];
    } else {                      // alphabetical-style: k, q, v
        k = (const float*)d_in[big[0]];
        q = (const float*)d_in[big[1]];
    }
    const float* v  = (const float*)d_in[big[2]];
    const float* w1 = (const float*)d_in[iw1];
    const float* b1 = (const float*)d_in[ibias[0]];
    const float* w2 = (const float*)d_in[iw2];
    const float* b2 = (const float*)d_in[ibias[1]];
    float* out = (float*)d_out;

    float *hbuf, *qphi, *kphi, *P, *Am;
    cudaGetSymbolAddress((void**)&hbuf, g_h);
    cudaGetSymbolAddress((void**)&qphi, g_qphi);
    cudaGetSymbolAddress((void**)&kphi, g_kphi);
    cudaGetSymbolAddress((void**)&P,    g_P);
    cudaGetSymbolAddress((void**)&Am,   g_A);

    const int TPB = 256;
    int nGemm = ROWS * FF;                       // 25,165,824
    int gGemm = (nGemm + TPB - 1) / TPB;

    // phi(q): h = silu(q@w1+b1); qphi = h@w2+b2
    gemm_naive<<<gGemm, TPB>>>(q,    w1, b1, hbuf, ROWS, DD, FF, 1);
    gemm_naive<<<gGemm, TPB>>>(hbuf, w2, b2, qphi, ROWS, FF, FF, 0);
    // phi(k)
    gemm_naive<<<gGemm, TPB>>>(k,    w1, b1, hbuf, ROWS, DD, FF, 1);
    gemm_naive<<<gGemm, TPB>>>(hbuf, w2, b2, kphi, ROWS, FF, FF, 0);

    // chunk states -> prefix
    int nCS = BH * NC * FF * DD;                 // 25,165,824
    chunk_state_naive<<<(nCS + TPB - 1) / TPB, TPB>>>(kphi, v, P);
    prefix_kernel<<<dim3(FD / 256, BH), 256>>>(P);

    // per-chunk scores
    int nSC = BH * NC * CHK * CHK;               // 12,582,912
    score_naive<<<(nSC + TPB - 1) / TPB, TPB>>>(qphi, kphi, Am);

    // final combine
    int nOut = BH * SEQ * DD;                    // 12,582,912
    out_naive<<<(nOut + TPB - 1) / TPB, TPB>>>(qphi, v, P, Am, out);
}

// round 4
// speedup vs baseline: 11.1199x; 11.1199x over previous
#include <cuda_runtime.h>

// Problem constants
#define BH   24
#define SEQ  4096
#define DD   128
#define FF   256
#define CHK  128
#define NC   32
#define ROWS (BH*SEQ)      // 98304
#define FD   (FF*DD)       // 32768

// ---------------- scratch (device globals; no runtime allocation) ----------
__device__ float g_h   [(size_t)ROWS * FF];
__device__ float g_qphi[(size_t)ROWS * FF];
__device__ float g_kphi[(size_t)ROWS * FF];
__device__ float g_P   [(size_t)BH * (NC+1) * FD];

// ---------------------------------------------------------------------------
// Tiled SGEMM: C[M,Nn] = act(A[M,K] @ W[K,Nn] + bias); act==1 -> SiLU.
// 128x128 tile, 256 threads, 8x8 micro-tile.
// ---------------------------------------------------------------------------
__global__ __launch_bounds__(256) void sgemm_bias_act(
    const float* __restrict__ A, const float* __restrict__ W,
    const float* __restrict__ bias, float* __restrict__ C,
    int M, int K, int Nn, int act)
{
    __shared__ float As[128][17];
    __shared__ float Bs[16][132];

    const int t  = threadIdx.x;
    const int tx = t & 15;
    const int ty = t >> 4;
    const int row0 = blockIdx.x * 128;
    const int col0 = blockIdx.y * 128;

    float acc[8][8];
#pragma unroll
    for (int i = 0; i < 8; i++)
#pragma unroll
        for (int j = 0; j < 8; j++) acc[i][j] = 0.f;

    for (int k0 = 0; k0 < K; k0 += 16) {
        // A tile: 128 rows x 16 k  = 2048 floats = 512 float4 slots
#pragma unroll
        for (int r = 0; r < 2; r++) {
            int idx = t + r * 256;
            int m   = idx >> 2;
            int kk  = (idx & 3) << 2;
            float4 v4 = *(const float4*)(A + (size_t)(row0 + m) * K + k0 + kk);
            As[m][kk+0] = v4.x; As[m][kk+1] = v4.y;
            As[m][kk+2] = v4.z; As[m][kk+3] = v4.w;
        }
        // B tile: 16 k x 128 n = 2048 floats = 512 slots
#pragma unroll
        for (int r = 0; r < 2; r++) {
            int idx = t + r * 256;
            int kk  = idx >> 5;
            int n4  = (idx & 31) << 2;
            *(float4*)&Bs[kk][n4] =
                *(const float4*)(W + (size_t)(k0 + kk) * Nn + col0 + n4);
        }
        __syncthreads();

#pragma unroll
        for (int k = 0; k < 16; k++) {
            float a[8], b[8];
#pragma unroll
            for (int i = 0; i < 8; i++) a[i] = As[ty * 8 + i][k];
            *(float4*)&b[0] = *(float4*)&Bs[k][tx * 4];
            *(float4*)&b[4] = *(float4*)&Bs[k][64 + tx * 4];
#pragma unroll
            for (int i = 0; i < 8; i++)
#pragma unroll
                for (int j = 0; j < 8; j++)
                    acc[i][j] += a[i] * b[j];
        }
        __syncthreads();
    }

#pragma unroll
    for (int i = 0; i < 8; i++) {
        int row = row0 + ty * 8 + i;
#pragma unroll
        for (int g = 0; g < 2; g++) {
            int col = col0 + g * 64 + tx * 4;
            float x0 = acc[i][g*4+0] + bias[col+0];
            float x1 = acc[i][g*4+1] + bias[col+1];
            float x2 = acc[i][g*4+2] + bias[col+2];
            float x3 = acc[i][g*4+3] + bias[col+3];
            if (act) {
                x0 = x0 / (1.f + __expf(-x0));
                x1 = x1 / (1.f + __expf(-x1));
                x2 = x2 / (1.f + __expf(-x2));
                x3 = x3 / (1.f + __expf(-x3));
            }
            float4 o; o.x = x0; o.y = x1; o.z = x2; o.w = x3;
            *(float4*)(C + (size_t)row * Nn + col) = o;
        }
    }
}

// ---------------------------------------------------------------------------
// Chunk state: S_c[f][d] = sum_m Kphi_c[m][f] * V_c[m][d]
// ---------------------------------------------------------------------------
__global__ __launch_bounds__(256) void chunk_state_kernel(
    const float* __restrict__ kphi, const float* __restrict__ vin,
    float* __restrict__ P)
{
    __shared__ float Ks[32][132];   // [m][f-tile]
    __shared__ float Vs[32][132];   // [m][d]

    const int t  = threadIdx.x;
    const int tx = t & 15;
    const int ty = t >> 4;
    const int hc = blockIdx.x;
    const int h  = hc >> 5;
    const int c  = hc & 31;
    const int f0 = blockIdx.y * 128;
    const int pos0 = h * SEQ + c * CHK;

    float acc[8][8];
#pragma unroll
    for (int i = 0; i < 8; i++)
#pragma unroll
        for (int j = 0; j < 8; j++) acc[i][j] = 0.f;

    for (int m0 = 0; m0 < CHK; m0 += 32) {
        // each tile: 32 rows x 128 floats = 4096 floats = 1024 slots
#pragma unroll
        for (int r = 0; r < 4; r++) {
            int idx = t + r * 256;
            int m   = idx >> 5;
            int f4  = (idx & 31) << 2;
            *(float4*)&Ks[m][f4] =
                *(const float4*)(kphi + (size_t)(pos0 + m0 + m) * FF + f0 + f4);
            *(float4*)&Vs[m][f4] =
                *(const float4*)(vin + (size_t)(pos0 + m0 + m) * DD + f4);
        }
        __syncthreads();

#pragma unroll
        for (int m = 0; m < 32; m++) {
            float a[8], b[8];
#pragma unroll
            for (int i = 0; i < 8; i++) a[i] = Ks[m][ty * 8 + i];
            *(float4*)&b[0] = *(float4*)&Vs[m][tx * 4];
            *(float4*)&b[4] = *(float4*)&Vs[m][64 + tx * 4];
#pragma unroll
            for (int i = 0; i < 8; i++)
#pragma unroll
                for (int j = 0; j < 8; j++)
                    acc[i][j] += a[i] * b[j];
        }
        __syncthreads();
    }

    float* S = P + ((size_t)(h * (NC + 1)) + (c + 1)) * FD;
#pragma unroll
    for (int i = 0; i < 8; i++) {
        int f = f0 + ty * 8 + i;
#pragma unroll
        for (int g = 0; g < 2; g++) {
            int d = g * 64 + tx * 4;
            float4 o;
            o.x = acc[i][g*4+0]; o.y = acc[i][g*4+1];
            o.z = acc[i][g*4+2]; o.w = acc[i][g*4+3];
            *(float4*)(S + (size_t)f * DD + d) = o;
        }
    }
}

// ---------------------------------------------------------------------------
// Inclusive prefix over chunk slabs; slab 0 zeroed.
// ---------------------------------------------------------------------------
__global__ void prefix_kernel(float* __restrict__ P)
{
    const int h = blockIdx.y;
    const int e = blockIdx.x * 256 + threadIdx.x;
    float* base = P + (size_t)h * (NC + 1) * FD;
    base[e] = 0.f;
    float acc = 0.f;
#pragma unroll
    for (int c = 1; c <= NC; c++) {
        acc += base[(size_t)c * FD + e];
        base[(size_t)c * FD + e] = acc;
    }
}

// ---------------------------------------------------------------------------
// Output kernel: one block per (head, chunk).
// ---------------------------------------------------------------------------
#define PA 129
#define PV 132
#define PQ 33
#define SM4_FLOATS (128*PA + 128*PV + 128*PQ + 128*PQ)
#define SM4_BYTES  (SM4_FLOATS * 4)                      // 167424

__global__ __launch_bounds__(256, 1) void output_kernel(
    const float* __restrict__ qphi, const float* __restrict__ kphi,
    const float* __restrict__ vin,  const float* __restrict__ P,
    float* __restrict__ out)
{
    extern __shared__ float sm[];
    float* Asm = sm;                       // 128*129
    float* Vs  = sm + 128 * PA;            // 128*132
    float* Qs  = Vs + 128 * PV;            // 128*33
    float* Ks2 = Qs + 128 * PQ;            // 128*33
    float* Ws1 = Asm;                      // stage-3 alias (A dead by then)
    float* Ws2 = Asm + 32 * PV;

    const int t  = threadIdx.x;
    const int tx = t & 15;
    const int ty = t >> 4;
    const int hc = blockIdx.x;
    const int h  = hc >> 5;
    const int c  = hc & 31;
    const int pos0 = h * SEQ + c * CHK;

    // ---------------- Stage 1: A = Q_c K_c^T ----------------
    float accA[8][8];
#pragma unroll
    for (int i = 0; i < 8; i++)
#pragma unroll
        for (int j = 0; j < 8; j++) accA[i][j] = 0.f;

    for (int f0 = 0; f0 < FF; f0 += 32) {
        __syncthreads();
        // Q,K tiles: 128 rows x 32 f = 4096 floats = 1024 slots each
#pragma unroll
        for (int r = 0; r < 4; r++) {
            int idx = t + r * 256;
            int n   = idx >> 3;
            int f4  = (idx & 7) << 2;
            float4 qv = *(const float4*)(qphi + (size_t)(pos0 + n) * FF + f0 + f4);
            Qs[n*PQ + f4+0] = qv.x; Qs[n*PQ + f4+1] = qv.y;
            Qs[n*PQ + f4+2] = qv.z; Qs[n*PQ + f4+3] = qv.w;
            float4 kv = *(const float4*)(kphi + (size_t)(pos0 + n) * FF + f0 + f4);
            Ks2[n*PQ + f4+0] = kv.x; Ks2[n*PQ + f4+1] = kv.y;
            Ks2[n*PQ + f4+2] = kv.z; Ks2[n*PQ + f4+3] = kv.w;
        }
        __syncthreads();
#pragma unroll
        for (int f = 0; f < 32; f++) {
            float a[8], b[8];
#pragma unroll
            for (int i = 0; i < 8; i++) a[i] = Qs[(ty*8+i)*PQ + f];
#pragma unroll
            for (int j = 0; j < 4; j++) {
                b[j]   = Ks2[(tx*4+j)*PQ + f];
                b[4+j] = Ks2[(64+tx*4+j)*PQ + f];
            }
#pragma unroll
            for (int i = 0; i < 8; i++)
#pragma unroll
                for (int j = 0; j < 8; j++)
                    accA[i][j] += a[i] * b[j];
        }
    }
    __syncthreads();
    // write A to smem
#pragma unroll
    for (int i = 0; i < 8; i++) {
        int n = ty * 8 + i;
#pragma unroll
        for (int j = 0; j < 4; j++) {
            Asm[n*PA + tx*4 + j]      = accA[i][j];
            Asm[n*PA + 64 + tx*4 + j] = accA[i][4+j];
        }
    }
    // load V tile: 128 rows x 128 d = 16384 floats = 4096 float4 slots
    // (FIXED: was r<4 -> only 32 rows; must be r<16)
#pragma unroll
    for (int r = 0; r < 16; r++) {
        int idx = t + r * 256;          // 0..4095
        int m   = idx >> 5;             // 0..127
        int d4  = (idx & 31) << 2;      // 0..124
        *(float4*)&Vs[m*PV + d4] =
            *(const float4*)(vin + (size_t)(pos0 + m) * DD + d4);
    }
    __syncthreads();

    // ---------------- Stage 2: intra-chunk tril/triu @ V ----------------
    float acc1[8][8], acc2[8][8];
#pragma unroll
    for (int i = 0; i < 8; i++)
#pragma unroll
        for (int j = 0; j < 8; j++) { acc1[i][j] = 0.f; acc2[i][j] = 0.f; }

    for (int m = 0; m < CHK; m++) {
        float v0[4], v1[4];
        *(float4*)v0 = *(float4*)&Vs[m*PV + tx*4];
        *(float4*)v1 = *(float4*)&Vs[m*PV + 64 + tx*4];
#pragma unroll
        for (int i = 0; i < 8; i++) {
            int n = ty * 8 + i;
            float a  = Asm[n*PA + m];
            float af = (m <= n) ? a : 0.f;
            float ar = (m >= n) ? a : 0.f;
#pragma unroll
            for (int j = 0; j < 4; j++) {
                acc1[i][j]   += af * v0[j];
                acc1[i][4+j] += af * v1[j];
                acc2[i][j]   += ar * v0[j];
                acc2[i][4+j] += ar * v1[j];
            }
        }
    }

    // ---------------- Stage 3: inter-chunk Q @ Wexc / Q @ Wsuf ----------------
    const float* Pbase = P + (size_t)h * (NC + 1) * FD;
    const float* Pexc  = Pbase + (size_t)c * FD;
    const float* Pinc  = Pbase + (size_t)(c + 1) * FD;
    const float* Ptot  = Pbase + (size_t)NC * FD;

    for (int f0 = 0; f0 < FF; f0 += 32) {
        __syncthreads();   // Asm (stage2) / Ws+Qs (prev iter) now dead
        // Q tile: 128 x 32 = 1024 slots
#pragma unroll
        for (int r = 0; r < 4; r++) {
            int idx = t + r * 256;
            int n   = idx >> 3;
            int f4  = (idx & 7) << 2;
            float4 qv = *(const float4*)(qphi + (size_t)(pos0 + n) * FF + f0 + f4);
            Qs[n*PQ + f4+0] = qv.x; Qs[n*PQ + f4+1] = qv.y;
            Qs[n*PQ + f4+2] = qv.z; Qs[n*PQ + f4+3] = qv.w;
        }
        // W tiles: 32 f x 128 d = 4096 floats = 1024 slots
#pragma unroll
        for (int r = 0; r < 4; r++) {
            int idx = t + r * 256;
            int f   = idx >> 5;
            int d4  = (idx & 31) << 2;
            size_t go = (size_t)(f0 + f) * DD + d4;
            *(float4*)&Ws1[f*PV + d4] = *(const float4*)(Pexc + go);
            float4 iv = *(const float4*)(Pinc + go);
            float4 tv = *(const float4*)(Ptot + go);
            float4 s;
            s.x = tv.x - iv.x; s.y = tv.y - iv.y;
            s.z = tv.z - iv.z; s.w = tv.w - iv.w;
            *(float4*)&Ws2[f*PV + d4] = s;
        }
        __syncthreads();
#pragma unroll
        for (int f = 0; f < 32; f++) {
            float a[8];
#pragma unroll
            for (int i = 0; i < 8; i++) a[i] = Qs[(ty*8+i)*PQ + f];
            float w10[4], w11[4], w20[4], w21[4];
            *(float4*)w10 = *(float4*)&Ws1[f*PV + tx*4];
            *(float4*)w11 = *(float4*)&Ws1[f*PV + 64 + tx*4];
            *(float4*)w20 = *(float4*)&Ws2[f*PV + tx*4];
            *(float4*)w21 = *(float4*)&Ws2[f*PV + 64 + tx*4];
#pragma unroll
            for (int i = 0; i < 8; i++)
#pragma unroll
                for (int j = 0; j < 4; j++) {
                    acc1[i][j]   += a[i] * w10[j];
                    acc1[i][4+j] += a[i] * w11[j];
                    acc2[i][j]   += a[i] * w20[j];
                    acc2[i][4+j] += a[i] * w21[j];
                }
        }
    }

    // ---------------- Epilogue ----------------
#pragma unroll
    for (int i = 0; i < 8; i++) {
        int n   = ty * 8 + i;
        int pos = c * CHK + n;
        float s1 = 1.f / (float)(pos + 1);
        float s2 = 1.f / (float)(SEQ - pos);
        size_t rowoff = (size_t)(pos0 + n) * DD;
#pragma unroll
        for (int g = 0; g < 2; g++) {
            int d = g * 64 + tx * 4;
            float4 o;
            o.x = acc1[i][g*4+0] * s1 + acc2[i][g*4+0] * s2;
            o.y = acc1[i][g*4+1] * s1 + acc2[i][g*4+1] * s2;
            o.z = acc1[i][g*4+2] * s1 + acc2[i][g*4+2] * s2;
            o.w = acc1[i][g*4+3] * s1 + acc2[i][g*4+3] * s2;
            *(float4*)(out + rowoff + d) = o;
        }
    }
}

// ---------------------------------------------------------------------------
extern "C" void kernel_launch(void* const* d_in, const int* in_sizes, int n_in,
                              void* d_out, int out_size)
{
    (void)out_size;
    // Size-signature input classification (proven in R3).
    int big[3] = {0, 1, 2}; int nbig = 0;
    int iw1 = -1, iw2 = -1, ibias[2] = {-1, -1}; int nb = 0;
    for (int i = 0; i < n_in; i++) {
        long long s = in_sizes[i];
        if ((s == 12582912LL || s == 50331648LL) && nbig < 3) big[nbig++] = i;
        else if (s == 32768LL  || s == 131072LL) iw1 = i;
        else if (s == 65536LL  || s == 262144LL) iw2 = i;
        else if ((s == 256LL   || s == 1024LL) && nb < 2) ibias[nb++] = i;
    }
    if (nbig != 3 || iw1 < 0 || iw2 < 0 || nb != 2) {
        big[0] = 0; big[1] = 1; big[2] = 2;
        iw1 = 3; ibias[0] = 4; iw2 = 5; ibias[1] = 6;
    }
    const float *q, *k;
    if (big[0] == 0) {
        q = (const float*)d_in[big[0]];
        k = (const float*)d_in[big[1]];
    } else {
        k = (const float*)d_in[big[0]];
        q = (const float*)d_in[big[1]];
    }
    const float* v  = (const float*)d_in[big[2]];
    const float* w1 = (const float*)d_in[iw1];
    const float* b1 = (const float*)d_in[ibias[0]];
    const float* w2 = (const float*)d_in[iw2];
    const float* b2 = (const float*)d_in[ibias[1]];
    float* out = (float*)d_out;

    float *hbuf, *qphi, *kphi, *P;
    cudaGetSymbolAddress((void**)&hbuf, g_h);
    cudaGetSymbolAddress((void**)&qphi, g_qphi);
    cudaGetSymbolAddress((void**)&kphi, g_kphi);
    cudaGetSymbolAddress((void**)&P,    g_P);

    dim3 gphi(ROWS / 128, FF / 128);    // (768, 2)

    sgemm_bias_act<<<gphi, 256>>>(q,    w1, b1, hbuf, ROWS, DD, FF, 1);
    sgemm_bias_act<<<gphi, 256>>>(hbuf, w2, b2, qphi, ROWS, FF, FF, 0);
    sgemm_bias_act<<<gphi, 256>>>(k,    w1, b1, hbuf, ROWS, DD, FF, 1);
    sgemm_bias_act<<<gphi, 256>>>(hbuf, w2, b2, kphi, ROWS, FF, FF, 0);

    chunk_state_kernel<<<dim3(BH * NC, 2), 256>>>(kphi, v, P);
    prefix_kernel<<<dim3(FD / 256, BH), 256>>>(P);

    cudaFuncSetAttribute(output_kernel,
                         cudaFuncAttributeMaxDynamicSharedMemorySize, SM4_BYTES);
    output_kernel<<<BH * NC, 256, SM4_BYTES>>>(qphi, kphi, v, P, out);
}

// round 6
// speedup vs baseline: 15.2415x; 1.3707x over previous
#include <cuda_runtime.h>
#include <cstdint>

// Problem constants
#define BH   24
#define SEQ  4096
#define DD   128
#define FF   256
#define CHK  128
#define NC   32
#define ROWS (BH*SEQ)      // 98304
#define FD   (FF*DD)       // 32768

// ---------------- scratch (device globals; no runtime allocation) ----------
__device__ float g_h   [(size_t)ROWS * FF];
__device__ float g_qphi[(size_t)ROWS * FF];
__device__ float g_kphi[(size_t)ROWS * FF];
__device__ float g_P   [(size_t)BH * (NC+1) * FD];
__device__ float g_w1t [FF * DD];    // w1^T : [256][128]
__device__ float g_w2t [FF * FF];    // w2^T : [256][256]

// ---------------------------------------------------------------------------
// tf32 warp-mma GEMM (mma.sync, sm_80+ PTX -> valid on compute_103):
//   C[row0:+128, col0:+128] = act(A @ Wt^T + bias)
//   A  : [M, K] row-major fp32 ;  Wt : [Nn, K] row-major fp32
// Block 128x128, 8 warps (2m x 4n), warp tile 64x32, k-tile 32.
// ---------------------------------------------------------------------------
#define GP 36   // smem row stride (floats): 4g+t bank-conflict-free frag reads

__device__ __forceinline__ uint32_t f2tf32(float x) {
    uint32_t r; asm("cvt.rna.tf32.f32 %0, %1;" : "=r"(r) : "f"(x)); return r;
}

__global__ __launch_bounds__(256) void tc_gemm(
    const float* __restrict__ A, const float* __restrict__ Wt,
    const float* __restrict__ bias, float* __restrict__ C,
    int K, int Nn, int act)
{
    __shared__ uint32_t As[128 * GP];
    __shared__ uint32_t Bs[128 * GP];

    const int t    = threadIdx.x;
    const int lane = t & 31;
    const int wid  = t >> 5;
    const int wm   = wid >> 2;        // 0..1
    const int wn   = wid & 3;         // 0..3
    const int g    = lane >> 2;       // 0..7
    const int tig  = lane & 3;        // 0..3
    const int row0 = blockIdx.x * 128;
    const int col0 = blockIdx.y * 128;

    float acc[4][4][4];
#pragma unroll
    for (int mt = 0; mt < 4; mt++)
#pragma unroll
        for (int nt = 0; nt < 4; nt++)
#pragma unroll
            for (int e = 0; e < 4; e++) acc[mt][nt][e] = 0.f;

    for (int k0 = 0; k0 < K; k0 += 32) {
        // ---- load tiles: 128 rows x 32 k each (1024 float4 slots) ----
#pragma unroll
        for (int r = 0; r < 4; r++) {
            int slot = t + r * 256;
            int row  = slot >> 3;
            int c4   = (slot & 7) << 2;
            float4 va = *(const float4*)(A + (size_t)(row0 + row) * K + k0 + c4);
            uint32_t* pa = &As[row * GP + c4];
            pa[0] = f2tf32(va.x); pa[1] = f2tf32(va.y);
            pa[2] = f2tf32(va.z); pa[3] = f2tf32(va.w);
            float4 vb = *(const float4*)(Wt + (size_t)(col0 + row) * K + k0 + c4);
            uint32_t* pb = &Bs[row * GP + c4];
            pb[0] = f2tf32(vb.x); pb[1] = f2tf32(vb.y);
            pb[2] = f2tf32(vb.z); pb[3] = f2tf32(vb.w);
        }
        __syncthreads();

        // ---- 4 k-steps of 8 ----
#pragma unroll
        for (int ks = 0; ks < 4; ks++) {
            int kc = ks * 8 + tig;
            uint32_t af[4][4];
#pragma unroll
            for (int mt = 0; mt < 4; mt++) {
                int base = (wm * 64 + mt * 16 + g) * GP + kc;
                af[mt][0] = As[base];
                af[mt][1] = As[base + 8 * GP];
                af[mt][2] = As[base + 4];
                af[mt][3] = As[base + 8 * GP + 4];
            }
            uint32_t bf[4][2];
#pragma unroll
            for (int nt = 0; nt < 4; nt++) {
                int base = (wn * 32 + nt * 8 + g) * GP + kc;
                bf[nt][0] = Bs[base];
                bf[nt][1] = Bs[base + 4];
            }
#pragma unroll
            for (int mt = 0; mt < 4; mt++)
#pragma unroll
                for (int nt = 0; nt < 4; nt++) {
                    asm volatile(
                        "mma.sync.aligned.m16n8k8.row.col.f32.tf32.tf32.f32 "
                        "{%0,%1,%2,%3}, {%4,%5,%6,%7}, {%8,%9}, {%0,%1,%2,%3};"
                        : "+f"(acc[mt][nt][0]), "+f"(acc[mt][nt][1]),
                          "+f"(acc[mt][nt][2]), "+f"(acc[mt][nt][3])
                        : "r"(af[mt][0]), "r"(af[mt][1]),
                          "r"(af[mt][2]), "r"(af[mt][3]),
                          "r"(bf[nt][0]), "r"(bf[nt][1]));
                }
        }
        __syncthreads();
    }

    // ---- epilogue: bias (+SiLU), store ----
#pragma unroll
    for (int mt = 0; mt < 4; mt++) {
#pragma unroll
        for (int nt = 0; nt < 4; nt++) {
            int row = row0 + wm * 64 + mt * 16 + g;
            int col = col0 + wn * 32 + nt * 8 + tig * 2;
            float b0v = bias[col], b1v = bias[col + 1];
            float x0 = acc[mt][nt][0] + b0v;
            float x1 = acc[mt][nt][1] + b1v;
            float x2 = acc[mt][nt][2] + b0v;
            float x3 = acc[mt][nt][3] + b1v;
            if (act) {
                x0 = x0 / (1.f + __expf(-x0));
                x1 = x1 / (1.f + __expf(-x1));
                x2 = x2 / (1.f + __expf(-x2));
                x3 = x3 / (1.f + __expf(-x3));
            }
            float2 o01; o01.x = x0; o01.y = x1;
            float2 o23; o23.x = x2; o23.y = x3;
            *(float2*)(C + (size_t)row * Nn + col)       = o01;
            *(float2*)(C + (size_t)(row + 8) * Nn + col) = o23;
        }
    }
}

// ---------------------------------------------------------------------------
// Transpose W [K,N] -> Wt [N,K]
// ---------------------------------------------------------------------------
__global__ void transpose_kernel(const float* __restrict__ W,
                                 float* __restrict__ Wt, int K, int N)
{
    int idx = blockIdx.x * blockDim.x + threadIdx.x;
    if (idx >= K * N) return;
    int kk = idx / N;
    int n  = idx - kk * N;
    Wt[(size_t)n * K + kk] = W[idx];
}

// ---------------------------------------------------------------------------
// Chunk state: S_c[f][d] = sum_m Kphi_c[m][f] * V_c[m][d]   (fp32, verified)
// ---------------------------------------------------------------------------
__global__ __launch_bounds__(256) void chunk_state_kernel(
    const float* __restrict__ kphi, const float* __restrict__ vin,
    float* __restrict__ P)
{
    __shared__ float Ks[32][132];
    __shared__ float Vs[32][132];

    const int t  = threadIdx.x;
    const int tx = t & 15;
    const int ty = t >> 4;
    const int hc = blockIdx.x;
    const int h  = hc >> 5;
    const int c  = hc & 31;
    const int f0 = blockIdx.y * 128;
    const int pos0 = h * SEQ + c * CHK;

    float acc[8][8];
#pragma unroll
    for (int i = 0; i < 8; i++)
#pragma unroll
        for (int j = 0; j < 8; j++) acc[i][j] = 0.f;

    for (int m0 = 0; m0 < CHK; m0 += 32) {
#pragma unroll
        for (int r = 0; r < 4; r++) {
            int idx = t + r * 256;
            int m   = idx >> 5;
            int f4  = (idx & 31) << 2;
            *(float4*)&Ks[m][f4] =
                *(const float4*)(kphi + (size_t)(pos0 + m0 + m) * FF + f0 + f4);
            *(float4*)&Vs[m][f4] =
                *(const float4*)(vin + (size_t)(pos0 + m0 + m) * DD + f4);
        }
        __syncthreads();

#pragma unroll
        for (int m = 0; m < 32; m++) {
            float a[8], b[8];
#pragma unroll
            for (int i = 0; i < 8; i++) a[i] = Ks[m][ty * 8 + i];
            *(float4*)&b[0] = *(float4*)&Vs[m][tx * 4];
            *(float4*)&b[4] = *(float4*)&Vs[m][64 + tx * 4];
#pragma unroll
            for (int i = 0; i < 8; i++)
#pragma unroll
                for (int j = 0; j < 8; j++)
                    acc[i][j] += a[i] * b[j];
        }
        __syncthreads();
    }

    float* S = P + ((size_t)(h * (NC + 1)) + (c + 1)) * FD;
#pragma unroll
    for (int i = 0; i < 8; i++) {
        int f = f0 + ty * 8 + i;
#pragma unroll
        for (int g = 0; g < 2; g++) {
            int d = g * 64 + tx * 4;
            float4 o;
            o.x = acc[i][g*4+0]; o.y = acc[i][g*4+1];
            o.z = acc[i][g*4+2]; o.w = acc[i][g*4+3];
            *(float4*)(S + (size_t)f * DD + d) = o;
        }
    }
}

// ---------------------------------------------------------------------------
// Inclusive prefix over chunk slabs; slab 0 zeroed.
// ---------------------------------------------------------------------------
__global__ void prefix_kernel(float* __restrict__ P)
{
    const int h = blockIdx.y;
    const int e = blockIdx.x * 256 + threadIdx.x;
    float* base = P + (size_t)h * (NC + 1) * FD;
    base[e] = 0.f;
    float acc = 0.f;
#pragma unroll
    for (int c = 1; c <= NC; c++) {
        acc += base[(size_t)c * FD + e];
        base[(size_t)c * FD + e] = acc;
    }
}

// ---------------------------------------------------------------------------
// Output kernel: one block per (head, chunk). (fp32, verified in R4)
// ---------------------------------------------------------------------------
#define PA 129
#define PV 132
#define PQ 33
#define SM4_FLOATS (128*PA + 128*PV + 128*PQ + 128*PQ)
#define SM4_BYTES  (SM4_FLOATS * 4)                      // 167424

__global__ __launch_bounds__(256, 1) void output_kernel(
    const float* __restrict__ qphi, const float* __restrict__ kphi,
    const float* __restrict__ vin,  const float* __restrict__ P,
    float* __restrict__ out)
{
    extern __shared__ float sm[];
    float* Asm = sm;
    float* Vs  = sm + 128 * PA;
    float* Qs  = Vs + 128 * PV;
    float* Ks2 = Qs + 128 * PQ;
    float* Ws1 = Asm;
    float* Ws2 = Asm + 32 * PV;

    const int t  = threadIdx.x;
    const int tx = t & 15;
    const int ty = t >> 4;
    const int hc = blockIdx.x;
    const int h  = hc >> 5;
    const int c  = hc & 31;
    const int pos0 = h * SEQ + c * CHK;

    float accA[8][8];
#pragma unroll
    for (int i = 0; i < 8; i++)
#pragma unroll
        for (int j = 0; j < 8; j++) accA[i][j] = 0.f;

    for (int f0 = 0; f0 < FF; f0 += 32) {
        __syncthreads();
#pragma unroll
        for (int r = 0; r < 4; r++) {
            int idx = t + r * 256;
            int n   = idx >> 3;
            int f4  = (idx & 7) << 2;
            float4 qv = *(const float4*)(qphi + (size_t)(pos0 + n) * FF + f0 + f4);
            Qs[n*PQ + f4+0] = qv.x; Qs[n*PQ + f4+1] = qv.y;
            Qs[n*PQ + f4+2] = qv.z; Qs[n*PQ + f4+3] = qv.w;
            float4 kv = *(const float4*)(kphi + (size_t)(pos0 + n) * FF + f0 + f4);
            Ks2[n*PQ + f4+0] = kv.x; Ks2[n*PQ + f4+1] = kv.y;
            Ks2[n*PQ + f4+2] = kv.z; Ks2[n*PQ + f4+3] = kv.w;
        }
        __syncthreads();
#pragma unroll
        for (int f = 0; f < 32; f++) {
            float a[8], b[8];
#pragma unroll
            for (int i = 0; i < 8; i++) a[i] = Qs[(ty*8+i)*PQ + f];
#pragma unroll
            for (int j = 0; j < 4; j++) {
                b[j]   = Ks2[(tx*4+j)*PQ + f];
                b[4+j] = Ks2[(64+tx*4+j)*PQ + f];
            }
#pragma unroll
            for (int i = 0; i < 8; i++)
#pragma unroll
                for (int j = 0; j < 8; j++)
                    accA[i][j] += a[i] * b[j];
        }
    }
    __syncthreads();
#pragma unroll
    for (int i = 0; i < 8; i++) {
        int n = ty * 8 + i;
#pragma unroll
        for (int j = 0; j < 4; j++) {
            Asm[n*PA + tx*4 + j]      = accA[i][j];
            Asm[n*PA + 64 + tx*4 + j] = accA[i][4+j];
        }
    }
#pragma unroll
    for (int r = 0; r < 16; r++) {
        int idx = t + r * 256;
        int m   = idx >> 5;
        int d4  = (idx & 31) << 2;
        *(float4*)&Vs[m*PV + d4] =
            *(const float4*)(vin + (size_t)(pos0 + m) * DD + d4);
    }
    __syncthreads();

    float acc1[8][8], acc2[8][8];
#pragma unroll
    for (int i = 0; i < 8; i++)
#pragma unroll
        for (int j = 0; j < 8; j++) { acc1[i][j] = 0.f; acc2[i][j] = 0.f; }

    for (int m = 0; m < CHK; m++) {
        float v0[4], v1[4];
        *(float4*)v0 = *(float4*)&Vs[m*PV + tx*4];
        *(float4*)v1 = *(float4*)&Vs[m*PV + 64 + tx*4];
#pragma unroll
        for (int i = 0; i < 8; i++) {
            int n = ty * 8 + i;
            float a  = Asm[n*PA + m];
            float af = (m <= n) ? a : 0.f;
            float ar = (m >= n) ? a : 0.f;
#pragma unroll
            for (int j = 0; j < 4; j++) {
                acc1[i][j]   += af * v0[j];
                acc1[i][4+j] += af * v1[j];
                acc2[i][j]   += ar * v0[j];
                acc2[i][4+j] += ar * v1[j];
            }
        }
    }

    const float* Pbase = P + (size_t)h * (NC + 1) * FD;
    const float* Pexc  = Pbase + (size_t)c * FD;
    const float* Pinc  = Pbase + (size_t)(c + 1) * FD;
    const float* Ptot  = Pbase + (size_t)NC * FD;

    for (int f0 = 0; f0 < FF; f0 += 32) {
        __syncthreads();
#pragma unroll
        for (int r = 0; r < 4; r++) {
            int idx = t + r * 256;
            int n   = idx >> 3;
            int f4  = (idx & 7) << 2;
            float4 qv = *(const float4*)(qphi + (size_t)(pos0 + n) * FF + f0 + f4);
            Qs[n*PQ + f4+0] = qv.x; Qs[n*PQ + f4+1] = qv.y;
            Qs[n*PQ + f4+2] = qv.z; Qs[n*PQ + f4+3] = qv.w;
        }
#pragma unroll
        for (int r = 0; r < 4; r++) {
            int idx = t + r * 256;
            int f   = idx >> 5;
            int d4  = (idx & 31) << 2;
            size_t go = (size_t)(f0 + f) * DD + d4;
            *(float4*)&Ws1[f*PV + d4] = *(const float4*)(Pexc + go);
            float4 iv = *(const float4*)(Pinc + go);
            float4 tv = *(const float4*)(Ptot + go);
            float4 s;
            s.x = tv.x - iv.x; s.y = tv.y - iv.y;
            s.z = tv.z - iv.z; s.w = tv.w - iv.w;
            *(float4*)&Ws2[f*PV + d4] = s;
        }
        __syncthreads();
#pragma unroll
        for (int f = 0; f < 32; f++) {
            float a[8];
#pragma unroll
            for (int i = 0; i < 8; i++) a[i] = Qs[(ty*8+i)*PQ + f];
            float w10[4], w11[4], w20[4], w21[4];
            *(float4*)w10 = *(float4*)&Ws1[f*PV + tx*4];
            *(float4*)w11 = *(float4*)&Ws1[f*PV + 64 + tx*4];
            *(float4*)w20 = *(float4*)&Ws2[f*PV + tx*4];
            *(float4*)w21 = *(float4*)&Ws2[f*PV + 64 + tx*4];
#pragma unroll
            for (int i = 0; i < 8; i++)
#pragma unroll
                for (int j = 0; j < 4; j++) {
                    acc1[i][j]   += a[i] * w10[j];
                    acc1[i][4+j] += a[i] * w11[j];
                    acc2[i][j]   += a[i] * w20[j];
                    acc2[i][4+j] += a[i] * w21[j];
                }
        }
    }

#pragma unroll
    for (int i = 0; i < 8; i++) {
        int n   = ty * 8 + i;
        int pos = c * CHK + n;
        float s1 = 1.f / (float)(pos + 1);
        float s2 = 1.f / (float)(SEQ - pos);
        size_t rowoff = (size_t)(pos0 + n) * DD;
#pragma unroll
        for (int g = 0; g < 2; g++) {
            int d = g * 64 + tx * 4;
            float4 o;
            o.x = acc1[i][g*4+0] * s1 + acc2[i][g*4+0] * s2;
            o.y = acc1[i][g*4+1] * s1 + acc2[i][g*4+1] * s2;
            o.z = acc1[i][g*4+2] * s1 + acc2[i][g*4+2] * s2;
            o.w = acc1[i][g*4+3] * s1 + acc2[i][g*4+3] * s2;
            *(float4*)(out + rowoff + d) = o;
        }
    }
}

// ---------------------------------------------------------------------------
extern "C" void kernel_launch(void* const* d_in, const int* in_sizes, int n_in,
                              void* d_out, int out_size)
{
    (void)out_size;
    int big[3] = {0, 1, 2}; int nbig = 0;
    int iw1 = -1, iw2 = -1, ibias[2] = {-1, -1}; int nb = 0;
    for (int i = 0; i < n_in; i++) {
        long long s = in_sizes[i];
        if ((s == 12582912LL || s == 50331648LL) && nbig < 3) big[nbig++] = i;
        else if (s == 32768LL  || s == 131072LL) iw1 = i;
        else if (s == 65536LL  || s == 262144LL) iw2 = i;
        else if ((s == 256LL   || s == 1024LL) && nb < 2) ibias[nb++] = i;
    }
    if (nbig != 3 || iw1 < 0 || iw2 < 0 || nb != 2) {
        big[0] = 0; big[1] = 1; big[2] = 2;
        iw1 = 3; ibias[0] = 4; iw2 = 5; ibias[1] = 6;
    }
    const float *q, *k;
    if (big[0] == 0) {
        q = (const float*)d_in[big[0]];
        k = (const float*)d_in[big[1]];
    } else {
        k = (const float*)d_in[big[0]];
        q = (const float*)d_in[big[1]];
    }
    const float* v  = (const float*)d_in[big[2]];
    const float* w1 = (const float*)d_in[iw1];
    const float* b1 = (const float*)d_in[ibias[0]];
    const float* w2 = (const float*)d_in[iw2];
    const float* b2 = (const float*)d_in[ibias[1]];
    float* out = (float*)d_out;

    float *hbuf, *qphi, *kphi, *P, *w1t, *w2t;
    cudaGetSymbolAddress((void**)&hbuf, g_h);
    cudaGetSymbolAddress((void**)&qphi, g_qphi);
    cudaGetSymbolAddress((void**)&kphi, g_kphi);
    cudaGetSymbolAddress((void**)&P,    g_P);
    cudaGetSymbolAddress((void**)&w1t,  g_w1t);
    cudaGetSymbolAddress((void**)&w2t,  g_w2t);

    cudaFuncSetAttribute(output_kernel,
                         cudaFuncAttributeMaxDynamicSharedMemorySize, SM4_BYTES);

    // transpose weights (tiny)
    transpose_kernel<<<(DD*FF + 255)/256, 256>>>(w1, w1t, DD, FF);
    transpose_kernel<<<(FF*FF + 255)/256, 256>>>(w2, w2t, FF, FF);

    // phi GEMMs on tensor cores (tf32 mma.sync)
    dim3 g1(ROWS / 128, FF / 128);      // (768, 2)
    tc_gemm<<<g1, 256>>>(q,    w1t, b1, hbuf, DD, FF, 1);
    tc_gemm<<<g1, 256>>>(hbuf, w2t, b2, qphi, FF, FF, 0);
    tc_gemm<<<g1, 256>>>(k,    w1t, b1, hbuf, DD, FF, 1);
    tc_gemm<<<g1, 256>>>(hbuf, w2t, b2, kphi, FF, FF, 0);

    // chunk states + prefix (fp32)
    chunk_state_kernel<<<dim3(BH * NC, 2), 256>>>(kphi, v, P);
    prefix_kernel<<<dim3(FD / 256, BH), 256>>>(P);

    // output (fp32)
    output_kernel<<<BH * NC, 256, SM4_BYTES>>>(qphi, kphi, v, P, out);
}

// round 7
// speedup vs baseline: 23.8699x; 1.5661x over previous
#include <cuda_runtime.h>
#include <cstdint>

// Problem constants
#define BH   24
#define SEQ  4096
#define DD   128
#define FF   256
#define CHK  128
#define NC   32
#define ROWS (BH*SEQ)      // 98304
#define FD   (FF*DD)       // 32768

// ---------------- scratch (device globals; no runtime allocation) ----------
__device__ float g_h   [(size_t)ROWS * FF];
__device__ float g_qphi[(size_t)ROWS * FF];
__device__ float g_kphi[(size_t)ROWS * FF];
__device__ float g_P   [(size_t)BH * (NC+1) * FD];   // TRANSPOSED slabs: [d][f]
__device__ float g_w1t [FF * DD];
__device__ float g_w2t [FF * FF];

#define GP  36    // straight k-chunk tile stride  (36 % 32 == 4 -> frag-read conflict-free)
#define GPT 37    // transposed k-chunk tile stride
#define AP  132   // full A matrix stride (132 % 32 == 4)
#define VP  133   // transposed V matrix stride

__device__ __forceinline__ uint32_t f2tf32(float x) {
    uint32_t r; asm("cvt.rna.tf32.f32 %0, %1;" : "=r"(r) : "f"(x)); return r;
}
__device__ __forceinline__ void mma8(float* c, const uint32_t* a, const uint32_t* b) {
    asm volatile(
        "mma.sync.aligned.m16n8k8.row.col.f32.tf32.tf32.f32 "
        "{%0,%1,%2,%3}, {%4,%5,%6,%7}, {%8,%9}, {%0,%1,%2,%3};"
        : "+f"(c[0]), "+f"(c[1]), "+f"(c[2]), "+f"(c[3])
        : "r"(a[0]), "r"(a[1]), "r"(a[2]), "r"(a[3]), "r"(b[0]), "r"(b[1]));
}

// ---------------------------------------------------------------------------
// tf32 warp-mma GEMM (verified R6): C = act(A @ Wt^T + bias)
// ---------------------------------------------------------------------------
__global__ __launch_bounds__(256) void tc_gemm(
    const float* __restrict__ A, const float* __restrict__ Wt,
    const float* __restrict__ bias, float* __restrict__ C,
    int K, int Nn, int act)
{
    __shared__ uint32_t As[128 * GP];
    __shared__ uint32_t Bs[128 * GP];

    const int t    = threadIdx.x;
    const int lane = t & 31;
    const int wid  = t >> 5;
    const int wm   = wid >> 2;
    const int wn   = wid & 3;
    const int g    = lane >> 2;
    const int tig  = lane & 3;
    const int row0 = blockIdx.x * 128;
    const int col0 = blockIdx.y * 128;

    float acc[4][4][4];
#pragma unroll
    for (int mt = 0; mt < 4; mt++)
#pragma unroll
        for (int nt = 0; nt < 4; nt++)
#pragma unroll
            for (int e = 0; e < 4; e++) acc[mt][nt][e] = 0.f;

    for (int k0 = 0; k0 < K; k0 += 32) {
#pragma unroll
        for (int r = 0; r < 4; r++) {
            int slot = t + r * 256;
            int row  = slot >> 3;
            int c4   = (slot & 7) << 2;
            float4 va = *(const float4*)(A + (size_t)(row0 + row) * K + k0 + c4);
            uint32_t* pa = &As[row * GP + c4];
            pa[0] = f2tf32(va.x); pa[1] = f2tf32(va.y);
            pa[2] = f2tf32(va.z); pa[3] = f2tf32(va.w);
            float4 vb = *(const float4*)(Wt + (size_t)(col0 + row) * K + k0 + c4);
            uint32_t* pb = &Bs[row * GP + c4];
            pb[0] = f2tf32(vb.x); pb[1] = f2tf32(vb.y);
            pb[2] = f2tf32(vb.z); pb[3] = f2tf32(vb.w);
        }
        __syncthreads();
#pragma unroll
        for (int ks = 0; ks < 4; ks++) {
            int kc = ks * 8 + tig;
            uint32_t af[4][4];
#pragma unroll
            for (int mt = 0; mt < 4; mt++) {
                int base = (wm * 64 + mt * 16 + g) * GP + kc;
                af[mt][0] = As[base];
                af[mt][1] = As[base + 8 * GP];
                af[mt][2] = As[base + 4];
                af[mt][3] = As[base + 8 * GP + 4];
            }
            uint32_t bf[4][2];
#pragma unroll
            for (int nt = 0; nt < 4; nt++) {
                int base = (wn * 32 + nt * 8 + g) * GP + kc;
                bf[nt][0] = Bs[base];
                bf[nt][1] = Bs[base + 4];
            }
#pragma unroll
            for (int mt = 0; mt < 4; mt++)
#pragma unroll
                for (int nt = 0; nt < 4; nt++)
                    mma8(acc[mt][nt], af[mt], bf[nt]);
        }
        __syncthreads();
    }

#pragma unroll
    for (int mt = 0; mt < 4; mt++) {
#pragma unroll
        for (int nt = 0; nt < 4; nt++) {
            int row = row0 + wm * 64 + mt * 16 + g;
            int col = col0 + wn * 32 + nt * 8 + tig * 2;
            float b0v = bias[col], b1v = bias[col + 1];
            float x0 = acc[mt][nt][0] + b0v;
            float x1 = acc[mt][nt][1] + b1v;
            float x2 = acc[mt][nt][2] + b0v;
            float x3 = acc[mt][nt][3] + b1v;
            if (act) {
                x0 = x0 / (1.f + __expf(-x0));
                x1 = x1 / (1.f + __expf(-x1));
                x2 = x2 / (1.f + __expf(-x2));
                x3 = x3 / (1.f + __expf(-x3));
            }
            float2 o01; o01.x = x0; o01.y = x1;
            float2 o23; o23.x = x2; o23.y = x3;
            *(float2*)(C + (size_t)row * Nn + col)       = o01;
            *(float2*)(C + (size_t)(row + 8) * Nn + col) = o23;
        }
    }
}

// ---------------------------------------------------------------------------
// Transpose W [K,N] -> Wt [N,K]
// ---------------------------------------------------------------------------
__global__ void transpose_kernel(const float* __restrict__ W,
                                 float* __restrict__ Wt, int K, int N)
{
    int idx = blockIdx.x * blockDim.x + threadIdx.x;
    if (idx >= K * N) return;
    int kk = idx / N;
    int n  = idx - kk * N;
    Wt[(size_t)n * K + kk] = W[idx];
}

// ---------------------------------------------------------------------------
// chunk_state (tensor cores): S^T[d][f] = sum_m V[m][d] * Kphi[m][f]
// Writes TRANSPOSED slab (c+1) of g_P ([d][f] layout, row stride FF).
// grid (BH*NC, 2): blockIdx.y = f-block of 128. M=d=128, N=f=128, K=m=128.
// ---------------------------------------------------------------------------
__global__ __launch_bounds__(256) void chunk_state_tc(
    const float* __restrict__ kphi, const float* __restrict__ vin,
    float* __restrict__ P)
{
    __shared__ uint32_t At[128 * GPT];   // V^T tile  [d][m-chunk]
    __shared__ uint32_t Bt[128 * GPT];   // K^T tile  [f][m-chunk]

    const int t    = threadIdx.x;
    const int lane = t & 31;
    const int wid  = t >> 5;
    const int wm   = wid >> 2;
    const int wn   = wid & 3;
    const int g    = lane >> 2;
    const int tig  = lane & 3;
    const int hc   = blockIdx.x;
    const int h    = hc >> 5;
    const int c    = hc & 31;
    const int f0   = blockIdx.y * 128;
    const int pos0 = h * SEQ + c * CHK;

    float acc[4][4][4];
#pragma unroll
    for (int mt = 0; mt < 4; mt++)
#pragma unroll
        for (int nt = 0; nt < 4; nt++)
#pragma unroll
            for (int e = 0; e < 4; e++) acc[mt][nt][e] = 0.f;

    for (int m0 = 0; m0 < CHK; m0 += 32) {
        // transposed tile loads: rows m from gmem -> columns of At/Bt
#pragma unroll
        for (int r = 0; r < 4; r++) {
            int slot = t + r * 256;          // 1024 float4 slots
            int m    = slot >> 5;            // 0..31
            int x4   = (slot & 31) << 2;     // 0..124
            float4 vv = *(const float4*)(vin + (size_t)(pos0 + m0 + m) * DD + x4);
            At[(x4+0)*GPT + m] = f2tf32(vv.x);
            At[(x4+1)*GPT + m] = f2tf32(vv.y);
            At[(x4+2)*GPT + m] = f2tf32(vv.z);
            At[(x4+3)*GPT + m] = f2tf32(vv.w);
            float4 kk = *(const float4*)(kphi + (size_t)(pos0 + m0 + m) * FF + f0 + x4);
            Bt[(x4+0)*GPT + m] = f2tf32(kk.x);
            Bt[(x4+1)*GPT + m] = f2tf32(kk.y);
            Bt[(x4+2)*GPT + m] = f2tf32(kk.z);
            Bt[(x4+3)*GPT + m] = f2tf32(kk.w);
        }
        __syncthreads();
#pragma unroll
        for (int ks = 0; ks < 4; ks++) {
            int kc = ks * 8 + tig;
            uint32_t af[4][4];
#pragma unroll
            for (int mt = 0; mt < 4; mt++) {
                int base = (wm * 64 + mt * 16 + g) * GPT + kc;
                af[mt][0] = At[base];
                af[mt][1] = At[base + 8 * GPT];
                af[mt][2] = At[base + 4];
                af[mt][3] = At[base + 8 * GPT + 4];
            }
            uint32_t bf[4][2];
#pragma unroll
            for (int nt = 0; nt < 4; nt++) {
                int base = (wn * 32 + nt * 8 + g) * GPT + kc;
                bf[nt][0] = Bt[base];
                bf[nt][1] = Bt[base + 4];
            }
#pragma unroll
            for (int mt = 0; mt < 4; mt++)
#pragma unroll
                for (int nt = 0; nt < 4; nt++)
                    mma8(acc[mt][nt], af[mt], bf[nt]);
        }
        __syncthreads();
    }

    float* S = P + ((size_t)(h * (NC + 1)) + (c + 1)) * FD;   // [d][f] layout
#pragma unroll
    for (int mt = 0; mt < 4; mt++) {
#pragma unroll
        for (int nt = 0; nt < 4; nt++) {
            int d   = wm * 64 + mt * 16 + g;
            int col = f0 + wn * 32 + nt * 8 + tig * 2;
            float2 o01; o01.x = acc[mt][nt][0]; o01.y = acc[mt][nt][1];
            float2 o23; o23.x = acc[mt][nt][2]; o23.y = acc[mt][nt][3];
            *(float2*)(S + (size_t)d * FF + col)       = o01;
            *(float2*)(S + (size_t)(d + 8) * FF + col) = o23;
        }
    }
}

// ---------------------------------------------------------------------------
// Inclusive prefix over chunk slabs (elementwise; layout-agnostic).
// ---------------------------------------------------------------------------
__global__ void prefix_kernel(float* __restrict__ P)
{
    const int h = blockIdx.y;
    const int e = blockIdx.x * 256 + threadIdx.x;
    float* base = P + (size_t)h * (NC + 1) * FD;
    base[e] = 0.f;
    float acc = 0.f;
#pragma unroll
    for (int c = 1; c <= NC; c++) {
        acc += base[(size_t)c * FD + e];
        base[(size_t)c * FD + e] = acc;
    }
}

// ---------------------------------------------------------------------------
// output_tc: one block per (head, chunk), 256 thr, all-tensor-core.
//   S1: A = Qphi Kphi^T (K=256) -> tf32 A in smem [n][m]
//   S2: acc1 += tril(A)@V, acc2 += triu(A)@V (masking at fragment load)
//   S3: acc1 += Q@Wexc, acc2 += Q@Wsuf  (P stored [d][f] -> straight B tiles)
//   epilogue: out = acc1/(pos+1) + acc2/(SEQ-pos)
// ---------------------------------------------------------------------------
#define OSM_BYTES ((128*AP + 128*VP) * 4)   // 135680

__global__ __launch_bounds__(256, 1) void output_tc(
    const float* __restrict__ qphi, const float* __restrict__ kphi,
    const float* __restrict__ vin,  const float* __restrict__ P,
    float* __restrict__ out)
{
    extern __shared__ uint32_t smx[];
    uint32_t* Abuf = smx;                 // 128*AP   (tf32 A; stage3 tiles alias)
    uint32_t* Vt   = smx + 128 * AP;      // 128*VP   (V^T; stage1 tiles alias)
    uint32_t* S1Q  = Vt;                  // 128*GP
    uint32_t* S1K  = Vt + 128 * GP;       // 128*GP
    uint32_t* S3Q  = Abuf;                // 128*GP
    uint32_t* S3B1 = Abuf + 128 * GP;     // 128*GP
    uint32_t* S3B2 = Abuf + 2 * 128 * GP; // 128*GP

    const int t    = threadIdx.x;
    const int lane = t & 31;
    const int wid  = t >> 5;
    const int wm   = wid >> 2;
    const int wn   = wid & 3;
    const int g    = lane >> 2;
    const int tig  = lane & 3;
    const int hc   = blockIdx.x;
    const int h    = hc >> 5;
    const int c    = hc & 31;
    const int pos0 = h * SEQ + c * CHK;

    // ================= Stage 1: A = Qphi Kphi^T (K=256) =================
    float accA[4][4][4];
#pragma unroll
    for (int mt = 0; mt < 4; mt++)
#pragma unroll
        for (int nt = 0; nt < 4; nt++)
#pragma unroll
            for (int e = 0; e < 4; e++) accA[mt][nt][e] = 0.f;

    for (int f0 = 0; f0 < FF; f0 += 32) {
        __syncthreads();
#pragma unroll
        for (int r = 0; r < 4; r++) {
            int slot = t + r * 256;
            int row  = slot >> 3;
            int c4   = (slot & 7) << 2;
            float4 qv = *(const float4*)(qphi + (size_t)(pos0 + row) * FF + f0 + c4);
            uint32_t* pq = &S1Q[row * GP + c4];
            pq[0] = f2tf32(qv.x); pq[1] = f2tf32(qv.y);
            pq[2] = f2tf32(qv.z); pq[3] = f2tf32(qv.w);
            float4 kv = *(const float4*)(kphi + (size_t)(pos0 + row) * FF + f0 + c4);
            uint32_t* pk = &S1K[row * GP + c4];
            pk[0] = f2tf32(kv.x); pk[1] = f2tf32(kv.y);
            pk[2] = f2tf32(kv.z); pk[3] = f2tf32(kv.w);
        }
        __syncthreads();
#pragma unroll
        for (int ks = 0; ks < 4; ks++) {
            int kc = ks * 8 + tig;
            uint32_t af[4][4];
#pragma unroll
            for (int mt = 0; mt < 4; mt++) {
                int base = (wm * 64 + mt * 16 + g) * GP + kc;
                af[mt][0] = S1Q[base];
                af[mt][1] = S1Q[base + 8 * GP];
                af[mt][2] = S1Q[base + 4];
                af[mt][3] = S1Q[base + 8 * GP + 4];
            }
            uint32_t bf[4][2];
#pragma unroll
            for (int nt = 0; nt < 4; nt++) {
                int base = (wn * 32 + nt * 8 + g) * GP + kc;
                bf[nt][0] = S1K[base];
                bf[nt][1] = S1K[base + 4];
            }
#pragma unroll
            for (int mt = 0; mt < 4; mt++)
#pragma unroll
                for (int nt = 0; nt < 4; nt++)
                    mma8(accA[mt][nt], af[mt], bf[nt]);
        }
    }
    __syncthreads();   // all warps done with S1Q/S1K reads

    // write A (tf32) to Abuf [n][m]; load V^T into Vt (overwrites S1 region)
#pragma unroll
    for (int mt = 0; mt < 4; mt++) {
#pragma unroll
        for (int nt = 0; nt < 4; nt++) {
            int n0 = wm * 64 + mt * 16 + g;
            int m0 = wn * 32 + nt * 8 + tig * 2;
            Abuf[n0 * AP + m0]           = f2tf32(accA[mt][nt][0]);
            Abuf[n0 * AP + m0 + 1]       = f2tf32(accA[mt][nt][1]);
            Abuf[(n0 + 8) * AP + m0]     = f2tf32(accA[mt][nt][2]);
            Abuf[(n0 + 8) * AP + m0 + 1] = f2tf32(accA[mt][nt][3]);
        }
    }
#pragma unroll
    for (int r = 0; r < 16; r++) {
        int slot = t + r * 256;          // 4096 float4 slots
        int m    = slot >> 5;            // 0..127
        int d4   = (slot & 31) << 2;     // 0..124
        float4 vv = *(const float4*)(vin + (size_t)(pos0 + m) * DD + d4);
        Vt[(d4+0)*VP + m] = f2tf32(vv.x);
        Vt[(d4+1)*VP + m] = f2tf32(vv.y);
        Vt[(d4+2)*VP + m] = f2tf32(vv.z);
        Vt[(d4+3)*VP + m] = f2tf32(vv.w);
    }
    __syncthreads();

    // ================= Stage 2: masked A @ V =================
    float acc1[4][4][4], acc2[4][4][4];
#pragma unroll
    for (int mt = 0; mt < 4; mt++)
#pragma unroll
        for (int nt = 0; nt < 4; nt++)
#pragma unroll
            for (int e = 0; e < 4; e++) { acc1[mt][nt][e] = 0.f; acc2[mt][nt][e] = 0.f; }

#pragma unroll
    for (int kch = 0; kch < 4; kch++) {
#pragma unroll
        for (int ks = 0; ks < 4; ks++) {
            int kc = kch * 32 + ks * 8 + tig;    // m index (col of A)
            uint32_t lo[4][4], up[4][4];
#pragma unroll
            for (int mt = 0; mt < 4; mt++) {
                int nA = wm * 64 + mt * 16 + g;  // row of A (query pos)
                int nB = nA + 8;
                uint32_t a0 = Abuf[nA * AP + kc];
                uint32_t a1 = Abuf[nB * AP + kc];
                uint32_t a2 = Abuf[nA * AP + kc + 4];
                uint32_t a3 = Abuf[nB * AP + kc + 4];
                lo[mt][0] = (kc     <= nA) ? a0 : 0u;
                lo[mt][1] = (kc     <= nB) ? a1 : 0u;
                lo[mt][2] = (kc + 4 <= nA) ? a2 : 0u;
                lo[mt][3] = (kc + 4 <= nB) ? a3 : 0u;
                up[mt][0] = (kc     >= nA) ? a0 : 0u;
                up[mt][1] = (kc     >= nB) ? a1 : 0u;
                up[mt][2] = (kc + 4 >= nA) ? a2 : 0u;
                up[mt][3] = (kc + 4 >= nB) ? a3 : 0u;
            }
            uint32_t bf[4][2];
#pragma unroll
            for (int nt = 0; nt < 4; nt++) {
                int base = (wn * 32 + nt * 8 + g) * VP + kc;
                bf[nt][0] = Vt[base];
                bf[nt][1] = Vt[base + 4];
            }
#pragma unroll
            for (int mt = 0; mt < 4; mt++)
#pragma unroll
                for (int nt = 0; nt < 4; nt++) {
                    mma8(acc1[mt][nt], lo[mt], bf[nt]);
                    mma8(acc2[mt][nt], up[mt], bf[nt]);
                }
        }
    }
    __syncthreads();   // done reading Abuf/Vt; stage3 overwrites Abuf region

    // ================= Stage 3: Q @ Wexc / Q @ Wsuf =================
    const float* Pbase = P + (size_t)h * (NC + 1) * FD;     // [d][f] slabs
    const float* Pexc  = Pbase + (size_t)c * FD;
    const float* Pinc  = Pbase + (size_t)(c + 1) * FD;
    const float* Ptot  = Pbase + (size_t)NC * FD;

    for (int f0 = 0; f0 < FF; f0 += 32) {
#pragma unroll
        for (int r = 0; r < 4; r++) {
            int slot = t + r * 256;
            int row  = slot >> 3;            // n for Q; d for W tiles
            int c4   = (slot & 7) << 2;      // f-local
            float4 qv = *(const float4*)(qphi + (size_t)(pos0 + row) * FF + f0 + c4);
            uint32_t* pq = &S3Q[row * GP + c4];
            pq[0] = f2tf32(qv.x); pq[1] = f2tf32(qv.y);
            pq[2] = f2tf32(qv.z); pq[3] = f2tf32(qv.w);
            size_t go = (size_t)row * FF + f0 + c4;
            float4 ev = *(const float4*)(Pexc + go);
            uint32_t* p1 = &S3B1[row * GP + c4];
            p1[0] = f2tf32(ev.x); p1[1] = f2tf32(ev.y);
            p1[2] = f2tf32(ev.z); p1[3] = f2tf32(ev.w);
            float4 iv = *(const float4*)(Pinc + go);
            float4 tv = *(const float4*)(Ptot + go);
            uint32_t* p2 = &S3B2[row * GP + c4];
            p2[0] = f2tf32(tv.x - iv.x); p2[1] = f2tf32(tv.y - iv.y);
            p2[2] = f2tf32(tv.z - iv.z); p2[3] = f2tf32(tv.w - iv.w);
        }
        __syncthreads();
#pragma unroll
        for (int ks = 0; ks < 4; ks++) {
            int kc = ks * 8 + tig;
            uint32_t af[4][4];
#pragma unroll
            for (int mt = 0; mt < 4; mt++) {
                int base = (wm * 64 + mt * 16 + g) * GP + kc;
                af[mt][0] = S3Q[base];
                af[mt][1] = S3Q[base + 8 * GP];
                af[mt][2] = S3Q[base + 4];
                af[mt][3] = S3Q[base + 8 * GP + 4];
            }
            uint32_t b1[4][2], b2[4][2];
#pragma unroll
            for (int nt = 0; nt < 4; nt++) {
                int base = (wn * 32 + nt * 8 + g) * GP + kc;
                b1[nt][0] = S3B1[base];
                b1[nt][1] = S3B1[base + 4];
                b2[nt][0] = S3B2[base];
                b2[nt][1] = S3B2[base + 4];
            }
#pragma unroll
            for (int mt = 0; mt < 4; mt++)
#pragma unroll
                for (int nt = 0; nt < 4; nt++) {
                    mma8(acc1[mt][nt], af[mt], b1[nt]);
                    mma8(acc2[mt][nt], af[mt], b2[nt]);
                }
        }
        __syncthreads();
    }

    // ================= Epilogue =================
#pragma unroll
    for (int mt = 0; mt < 4; mt++) {
#pragma unroll
        for (int nt = 0; nt < 4; nt++) {
            int n0  = wm * 64 + mt * 16 + g;
            int d0  = wn * 32 + nt * 8 + tig * 2;
            int posA = c * CHK + n0;
            int posB = posA + 8;
            float s1a = 1.f / (float)(posA + 1);
            float s2a = 1.f / (float)(SEQ - posA);
            float s1b = 1.f / (float)(posB + 1);
            float s2b = 1.f / (float)(SEQ - posB);
            float2 oA, oB;
            oA.x = acc1[mt][nt][0] * s1a + acc2[mt][nt][0] * s2a;
            oA.y = acc1[mt][nt][1] * s1a + acc2[mt][nt][1] * s2a;
            oB.x = acc1[mt][nt][2] * s1b + acc2[mt][nt][2] * s2b;
            oB.y = acc1[mt][nt][3] * s1b + acc2[mt][nt][3] * s2b;
            *(float2*)(out + (size_t)(pos0 + n0) * DD + d0)     = oA;
            *(float2*)(out + (size_t)(pos0 + n0 + 8) * DD + d0) = oB;
        }
    }
}

// ---------------------------------------------------------------------------
extern "C" void kernel_launch(void* const* d_in, const int* in_sizes, int n_in,
                              void* d_out, int out_size)
{
    (void)out_size;
    int big[3] = {0, 1, 2}; int nbig = 0;
    int iw1 = -1, iw2 = -1, ibias[2] = {-1, -1}; int nb = 0;
    for (int i = 0; i < n_in; i++) {
        long long s = in_sizes[i];
        if ((s == 12582912LL || s == 50331648LL) && nbig < 3) big[nbig++] = i;
        else if (s == 32768LL  || s == 131072LL) iw1 = i;
        else if (s == 65536LL  || s == 262144LL) iw2 = i;
        else if ((s == 256LL   || s == 1024LL) && nb < 2) ibias[nb++] = i;
    }
    if (nbig != 3 || iw1 < 0 || iw2 < 0 || nb != 2) {
        big[0] = 0; big[1] = 1; big[2] = 2;
        iw1 = 3; ibias[0] = 4; iw2 = 5; ibias[1] = 6;
    }
    const float *q, *k;
    if (big[0] == 0) {
        q = (const float*)d_in[big[0]];
        k = (const float*)d_in[big[1]];
    } else {
        k = (const float*)d_in[big[0]];
        q = (const float*)d_in[big[1]];
    }
    const float* v  = (const float*)d_in[big[2]];
    const float* w1 = (const float*)d_in[iw1];
    const float* b1 = (const float*)d_in[ibias[0]];
    const float* w2 = (const float*)d_in[iw2];
    const float* b2 = (const float*)d_in[ibias[1]];
    float* out = (float*)d_out;

    float *hbuf, *qphi, *kphi, *P, *w1t, *w2t;
    cudaGetSymbolAddress((void**)&hbuf, g_h);
    cudaGetSymbolAddress((void**)&qphi, g_qphi);
    cudaGetSymbolAddress((void**)&kphi, g_kphi);
    cudaGetSymbolAddress((void**)&P,    g_P);
    cudaGetSymbolAddress((void**)&w1t,  g_w1t);
    cudaGetSymbolAddress((void**)&w2t,  g_w2t);

    cudaFuncSetAttribute(output_tc,
                         cudaFuncAttributeMaxDynamicSharedMemorySize, OSM_BYTES);

    transpose_kernel<<<(DD*FF + 255)/256, 256>>>(w1, w1t, DD, FF);
    transpose_kernel<<<(FF*FF + 255)/256, 256>>>(w2, w2t, FF, FF);

    dim3 g1(ROWS / 128, FF / 128);      // (768, 2)
    tc_gemm<<<g1, 256>>>(q,    w1t, b1, hbuf, DD, FF, 1);
    tc_gemm<<<g1, 256>>>(hbuf, w2t, b2, qphi, FF, FF, 0);
    tc_gemm<<<g1, 256>>>(k,    w1t, b1, hbuf, DD, FF, 1);
    tc_gemm<<<g1, 256>>>(hbuf, w2t, b2, kphi, FF, FF, 0);

    chunk_state_tc<<<dim3(BH * NC, 2), 256>>>(kphi, v, P);
    prefix_kernel<<<dim3(FD / 256, BH), 256>>>(P);

    output_tc<<<BH * NC, 256, OSM_BYTES>>>(qphi, kphi, v, P, out);
}